// round 14
// baseline (speedup 1.0000x reference)
#include <cuda_runtime.h>
#include <cstdint>

#define GRID     128
#define NTHREADS 512
#define NT       4096     // B*S tokens

// ---- device globals ----
__device__ float g_TEMB[4096 * 64];
__device__ unsigned g_arrive;
__device__ volatile unsigned g_release;

// ---- smem layout (floats), 58112 = 232448 B (exact max) ----
#define OFF_WQKV 0            // [k][192]      12288
#define OFF_WFC  12288        // [k][256]      16384
#define OFF_WPR  28672        // [k(256)][64]  16384
#define OFF_B    45056        // 448: bqkv[192] bfc[256]
#define OFF_X    45504        // 32 tokens pitch 65 = 2080
#define OFF_Q    47584        // Q[128] pitch 16 = 2048 (peer-pushed, bcast reads)
#define OFF_K    49632        // K[128] pitch 17 = 2176 (peer-pushed)
#define OFF_V    51808        // V[128] pitch 17 = 2176 (peer-pushed)
#define OFF_HA   53984        // h (LN out) / A landing zone, 32x65 = 2080
#define OFF_P    56064        // softmax P, 16 warps x 128 = 2048
#define OFF_HID  49632        // Phase-C hid 32 x pitch257 = 8222 (overlays K/V/HA/P)
#define SMEM_FLOATS 58112
#define SMEM_BYTES (SMEM_FLOATS * 4)   // 232448

// ---- packed f32x2 helpers ----
__device__ __forceinline__ unsigned long long bcast2(float x) {
    unsigned long long r; asm("mov.b64 %0,{%1,%1};" : "=l"(r) : "f"(x)); return r;
}
__device__ __forceinline__ void upk2(unsigned long long v, float& x, float& y) {
    asm("mov.b64 {%0,%1},%2;" : "=f"(x), "=f"(y) : "l"(v));
}
__device__ __forceinline__ void fma2(unsigned long long& d, unsigned long long a,
                                     unsigned long long b) {
    asm("fma.rn.f32x2 %0,%1,%2,%0;" : "+l"(d) : "l"(a), "l"(b));
}
__device__ __forceinline__ void add2(unsigned long long& d, unsigned long long a) {
    asm("add.rn.f32x2 %0,%0,%1;" : "+l"(d) : "l"(a));
}

// ---- cluster helpers ----
__device__ __forceinline__ uint32_t smem_u32(const void* p) {
    uint32_t a;
    asm("{ .reg .u64 t; cvta.to.shared.u64 t, %1; cvt.u32.u64 %0, t; }" : "=r"(a) : "l"(p));
    return a;
}
__device__ __forceinline__ void sts_cluster1(uint32_t laddr, int rank, float v) {
    uint32_t r;
    asm volatile("mapa.shared::cluster.u32 %0, %1, %2;" : "=r"(r) : "r"(laddr), "r"(rank));
    asm volatile("st.shared::cluster.f32 [%0], %1;" :: "r"(r), "f"(v) : "memory");
}
#define CLUSTER_BAR() do { \
    asm volatile("barrier.cluster.arrive.aligned;" ::: "memory"); \
    asm volatile("barrier.cluster.wait.aligned;"   ::: "memory"); \
} while (0)

__device__ __forceinline__ void grid_sync(unsigned gen) {
    __syncthreads();
    if (threadIdx.x == 0) {
        __threadfence();
        unsigned prev = atomicAdd(&g_arrive, 1u);
        if (prev == gen * GRID - 1u) {
            __threadfence();
            g_release = gen;
        } else {
            while (*(volatile unsigned*)&g_release < gen) { __nanosleep(32); }
        }
        __threadfence();
    }
    __syncthreads();
}

extern "C" __global__ void __launch_bounds__(NTHREADS, 1) __cluster_dims__(4, 1, 1)
lt37349035606833_kernel(
    const int*   __restrict__ idx,   const int*   __restrict__ nloops_p,
    const float* __restrict__ wte,   const float* __restrict__ wpe,
    const float* __restrict__ tw1,   const float* __restrict__ tb1,
    const float* __restrict__ tw2,   const float* __restrict__ tb2,
    const float* __restrict__ ln1g_, const float* __restrict__ ln1b_,
    const float* __restrict__ wqkv_, const float* __restrict__ bqkv_,
    const float* __restrict__ wo_,   const float* __restrict__ bo_,
    const float* __restrict__ ln2g_, const float* __restrict__ ln2b_,
    const float* __restrict__ wfc_,  const float* __restrict__ bfc_,
    const float* __restrict__ wpr_,  const float* __restrict__ bpr_,
    const float* __restrict__ lnfg_, const float* __restrict__ lnfb_,
    float* __restrict__ out)
{
    extern __shared__ float sm[];
    const int tid = threadIdx.x;
    const int blk = blockIdx.x;
    const int w = tid >> 5, l = tid & 31;
    const int nloops = *nloops_p;
    unsigned gen = g_release;
    const uint32_t smb = smem_u32(sm);

    // ---- stage weights/biases ----
    for (int i = tid; i < 12288; i += NTHREADS) sm[OFF_WQKV + i] = wqkv_[i];
    for (int i = tid; i < 16384; i += NTHREADS) {
        sm[OFF_WFC + i] = wfc_[i];
        sm[OFF_WPR + i] = wpr_[i];
    }
    if (tid < 192)                sm[OFF_B + tid] = bqkv_[tid];
    if (tid >= 192 && tid < 448)  sm[OFF_B + tid] = bfc_[tid - 192];

    // ln gamma/beta registerized (per-lane)
    const float ln1g0 = __ldg(ln1g_ + l), ln1g1 = __ldg(ln1g_ + 32 + l);
    const float ln1b0 = __ldg(ln1b_ + l), ln1b1 = __ldg(ln1b_ + 32 + l);
    const float ln2g0 = __ldg(ln2g_ + l), ln2g1 = __ldg(ln2g_ + 32 + l);
    const float ln2b0 = __ldg(ln2b_ + l), ln2b1 = __ldg(ln2b_ + 32 + l);

    // ---- initial x tile (pitch 65) ----
    const int t0 = blk * 32;
    for (int i = tid; i < 2048; i += NTHREADS) {
        int t = i >> 6, d = i & 63;
        int tok = t0 + t;
        sm[OFF_X + t * 65 + d] = wte[idx[tok] * 64 + d] + wpe[(tok & 127) * 64 + d];
    }
    __syncthreads();

    // ---- precompute temb (scratch in K/V region; grid_sync below) ----
    {
        float* sT = sm + OFF_K;
        for (int s = blk; s < nloops; s += GRID) {
            float tt = (float)s;
            if (tid < 128) {
                float f = __expf(-9.2103403719761836f * (float)tid / 128.0f);
                float a = tt * f;
                sT[tid]       = cosf(a);
                sT[128 + tid] = sinf(a);
            }
            __syncthreads();
            for (int j = tid; j < 1024; j += NTHREADS) {
                float z = tb1[j];
                for (int k = 0; k < 256; ++k) z += sT[k] * tw1[k * 1024 + j];
                sT[256 + j] = z / (1.0f + __expf(-z));
            }
            __syncthreads();
            if (tid < 64) {
                float z = tb2[tid];
                for (int k = 0; k < 1024; ++k) z += sT[256 + k] * tw2[k * 64 + tid];
                g_TEMB[s * 64 + tid] = z;
            }
            __syncthreads();
        }
    }
    grid_sync(++gen);

    const int rc = blk & 3;                  // cluster rank == head index
    float* sX   = sm + OFF_X;
    float* sHA  = sm + OFF_HA;               // h / A landing zone
    float* sHid = sm + OFF_HID;              // Phase-C hid (overlays K/V/HA/P)
    const float* sQ = sm + OFF_Q;
    const float* sK = sm + OFF_K;
    const float* sV = sm + OFF_V;
    const float* sWq = sm + OFF_WQKV;
    const float* sWf = sm + OFF_WFC;
    const float* sWp = sm + OFF_WPR;
    const float* sBq = sm + OFF_B;
    const float* sBf = sm + OFF_B + 192;

    // temb prefetch for it = 0
    float tv0 = __ldg(g_TEMB + l), tv1 = __ldg(g_TEMB + 32 + l);

    for (int it = 0; it < nloops; ++it) {
        // ============ Phase A: x += temb; LN1 -> sHA; QKV + push ============
        {
            #pragma unroll
            for (int t = 0; t < 2; ++t) {
                int lt = w * 2 + t;
                float x0 = sX[lt * 65 + l]      + tv0;
                float x1 = sX[lt * 65 + 32 + l] + tv1;
                sX[lt * 65 + l]      = x0;
                sX[lt * 65 + 32 + l] = x1;
                float s1 = x0 + x1, s2 = x0 * x0 + x1 * x1;
                #pragma unroll
                for (int o = 16; o; o >>= 1) {
                    s1 += __shfl_xor_sync(0xffffffffu, s1, o);
                    s2 += __shfl_xor_sync(0xffffffffu, s2, o);
                }
                float mu = s1 * (1.0f / 64.0f);
                float rs = rsqrtf(s2 * (1.0f / 64.0f) - mu * mu + 1e-5f);
                sHA[lt * 65 + l]      = (x0 - mu) * rs * ln1g0 + ln1b0;
                sHA[lt * 65 + 32 + l] = (x1 - mu) * rs * ln1g1 + ln1b1;
            }
        }
        __syncthreads();
        {   // QKV GEMM: warp -> 12 cols, lane -> token; push Q/K/V via DSMEM
            const int c0 = w * 12;
            const float* hAl = sHA + l * 65;
            unsigned long long acc[6] = {0, 0, 0, 0, 0, 0};
            #pragma unroll 4
            for (int k = 0; k < 64; ++k) {
                unsigned long long h2 = bcast2(hAl[k]);
                const float* wr = sWq + k * 192 + c0;
                ulonglong2 wa = *(const ulonglong2*)(wr);
                ulonglong2 wb = *(const ulonglong2*)(wr + 4);
                ulonglong2 wc = *(const ulonglong2*)(wr + 8);
                fma2(acc[0], h2, wa.x); fma2(acc[1], h2, wa.y);
                fma2(acc[2], h2, wb.x); fma2(acc[3], h2, wb.y);
                fma2(acc[4], h2, wc.x); fma2(acc[5], h2, wc.y);
            }
            float c[12];
            #pragma unroll
            for (int j = 0; j < 6; ++j) upk2(acc[j], c[2 * j], c[2 * j + 1]);
            const int tkb = rc * 32 + l;     // token within batch (0..127)
            #pragma unroll
            for (int g3 = 0; g3 < 3; ++g3) {
                int cg = c0 + 4 * g3;
                float v0 = c[4*g3]   + sBq[cg];
                float v1 = c[4*g3+1] + sBq[cg+1];
                float v2 = c[4*g3+2] + sBq[cg+2];
                float v3 = c[4*g3+3] + sBq[cg+3];
                uint32_t a; int tr;
                if (cg < 64) {
                    tr = cg >> 4;
                    a = smb + (OFF_Q + tkb * 16 + (cg & 15)) * 4;
                } else if (cg < 128) {
                    tr = (cg - 64) >> 4;
                    a = smb + (OFF_K + tkb * 17 + ((cg - 64) & 15)) * 4;
                } else {
                    tr = (cg - 128) >> 4;
                    a = smb + (OFF_V + tkb * 17 + ((cg - 128) & 15)) * 4;
                }
                sts_cluster1(a,      tr, v0);
                sts_cluster1(a + 4,  tr, v1);
                sts_cluster1(a + 8,  tr, v2);
                sts_cluster1(a + 12, tr, v3);
            }
        }
        CLUSTER_BAR();   // bar1: Q/K/V delivered everywhere

        // ============ Phase B: attention for head rc; Q/K/V local ============
        {
            float* sP = sm + OFF_P + w * 128;
            const int d = l & 15, half = l >> 4;
            #pragma unroll 1
            for (int r = 0; r < 8; ++r) {
                const int qt = w + 16 * r;          // interleaved -> warp balance
                const int gq = qt >> 5;
                const float* qb = sQ + qt * 16;     // broadcast LDS.128 x4
                float4 qa = *(const float4*)(qb);
                float4 qbv = *(const float4*)(qb + 4);
                float4 qc = *(const float4*)(qb + 8);
                float4 qd = *(const float4*)(qb + 12);
                float q[16] = {qa.x, qa.y, qa.z, qa.w, qbv.x, qbv.y, qbv.z, qbv.w,
                               qc.x, qc.y, qc.z, qc.w, qd.x, qd.y, qd.z, qd.w};
                float e[4];
                float mx = -1e30f;
                #pragma unroll
                for (int g = 0; g < 4; ++g) {
                    if (g > gq) break;
                    const float* Kr = sK + (32 * g + l) * 17;
                    float sA2 = 0.f, sB2 = 0.f;     // split score chain
                    #pragma unroll
                    for (int dd = 0; dd < 8; ++dd) sA2 += q[dd] * Kr[dd];
                    #pragma unroll
                    for (int dd = 8; dd < 16; ++dd) sB2 += q[dd] * Kr[dd];
                    float s = sA2 + sB2;
                    s = s * 0.25f + ((32 * g + l <= qt) ? 0.f : -1e9f);
                    e[g] = s;
                    mx = fmaxf(mx, s);
                }
                #pragma unroll
                for (int o = 16; o; o >>= 1) mx = fmaxf(mx, __shfl_xor_sync(0xffffffffu, mx, o));
                float es = 0.f;
                #pragma unroll
                for (int g = 0; g < 4; ++g) {
                    if (g > gq) break;
                    e[g] = __expf(e[g] - mx);
                    es += e[g];
                }
                #pragma unroll
                for (int o = 16; o; o >>= 1) es += __shfl_xor_sync(0xffffffffu, es, o);
                float inv = 1.0f / es;
                #pragma unroll
                for (int g = 0; g < 4; ++g) {
                    if (g > gq) break;
                    sP[32 * g + l] = e[g] * inv;
                }
                __syncwarp();
                float ov = 0.f;
                #pragma unroll
                for (int i = 0; i < 2; ++i) {
                    int g = half + 2 * i;
                    if (g <= gq) {
                        const float* Pg = sP + 32 * g;
                        const float* Vg = sV + (32 * g) * 17 + d;
                        const float* P1 = Pg + 16 * half;
                        const float* V1 = Vg + (16 * half) * 17;
                        const float* P2 = Pg + 16 - 16 * half;
                        const float* V2 = Vg + (16 - 16 * half) * 17;
                        float pvA = 0.f, pvB = 0.f;   // split PV chain
                        #pragma unroll
                        for (int k2 = 0; k2 < 16; ++k2) pvA += P1[k2] * V1[k2 * 17];
                        #pragma unroll
                        for (int k2 = 0; k2 < 16; ++k2) pvB += P2[k2] * V2[k2 * 17];
                        ov += pvA + pvB;
                    }
                }
                ov += __shfl_xor_sync(0xffffffffu, ov, 16);
                if (half == 0) {   // push A to token-owner CTA's sHA
                    sts_cluster1(smb + (OFF_HA + (qt & 31) * 65 + rc * 16 + d) * 4,
                                 qt >> 5, ov);
                }
                __syncwarp();
            }
        }
        CLUSTER_BAR();   // bar2: A delivered everywhere; Q/K/V/P dead from here

        // ============ Phase C: o-proj + LN2 + MLP (lane = token) ============
        {   // o-proj: warp -> 4 cols, lane -> token; 4 split chains
            const int c0o = w * 4;
            unsigned long long oa0 = 0, oa1 = 0, ob0 = 0, ob1 = 0;
            const float* sA = sHA + l * 65;
            #pragma unroll 8
            for (int k = 0; k < 64; k += 2) {
                unsigned long long a2 = bcast2(sA[k]);
                unsigned long long b2 = bcast2(sA[k + 1]);
                ulonglong2 wv0 = __ldg((const ulonglong2*)&wo_[k * 64 + c0o]);
                ulonglong2 wv1 = __ldg((const ulonglong2*)&wo_[(k + 1) * 64 + c0o]);
                fma2(oa0, a2, wv0.x); fma2(oa1, a2, wv0.y);
                fma2(ob0, b2, wv1.x); fma2(ob1, b2, wv1.y);
            }
            add2(oa0, ob0); add2(oa1, ob1);
            float o4[4];
            upk2(oa0, o4[0], o4[1]); upk2(oa1, o4[2], o4[3]);
            float4 bo4 = __ldg((const float4*)(bo_ + c0o));
            float* xr = sX + l * 65 + c0o;
            xr[0] += 0.1f * (o4[0] + bo4.x);
            xr[1] += 0.1f * (o4[1] + bo4.y);
            xr[2] += 0.1f * (o4[2] + bo4.z);
            xr[3] += 0.1f * (o4[3] + bo4.w);
        }
        __syncthreads();
        {   // LN2: 2 tokens/warp -> h in sHA (A fully consumed)
            #pragma unroll
            for (int t = 0; t < 2; ++t) {
                int lt = 2 * w + t;
                float x0 = sX[lt * 65 + l], x1 = sX[lt * 65 + 32 + l];
                float s1 = x0 + x1, s2 = x0 * x0 + x1 * x1;
                #pragma unroll
                for (int o = 16; o; o >>= 1) {
                    s1 += __shfl_xor_sync(0xffffffffu, s1, o);
                    s2 += __shfl_xor_sync(0xffffffffu, s2, o);
                }
                float mu = s1 * (1.f / 64.f);
                float rs = rsqrtf(s2 * (1.f / 64.f) - mu * mu + 1e-5f);
                sHA[lt * 65 + l]      = (x0 - mu) * rs * ln2g0 + ln2b0;
                sHA[lt * 65 + 32 + l] = (x1 - mu) * rs * ln2g1 + ln2b1;
            }
        }
        __syncthreads();
        float gl[16];
        {   // FC: warp -> 16 cols, lane -> token; gelu in regs
            const int c0f = w * 16;
            unsigned long long fac[8] = {0, 0, 0, 0, 0, 0, 0, 0};
            const float* sH = sHA + l * 65;
            #pragma unroll 2
            for (int k = 0; k < 64; ++k) {
                unsigned long long h2 = bcast2(sH[k]);
                const float* wr = sWf + k * 256 + c0f;
                ulonglong2 wa = *(const ulonglong2*)(wr);
                ulonglong2 wb = *(const ulonglong2*)(wr + 4);
                ulonglong2 wc = *(const ulonglong2*)(wr + 8);
                ulonglong2 wd = *(const ulonglong2*)(wr + 12);
                fma2(fac[0], h2, wa.x); fma2(fac[1], h2, wa.y);
                fma2(fac[2], h2, wb.x); fma2(fac[3], h2, wb.y);
                fma2(fac[4], h2, wc.x); fma2(fac[5], h2, wc.y);
                fma2(fac[6], h2, wd.x); fma2(fac[7], h2, wd.y);
            }
            float f[16];
            #pragma unroll
            for (int j = 0; j < 8; ++j) upk2(fac[j], f[2 * j], f[2 * j + 1]);
            #pragma unroll
            for (int j = 0; j < 16; ++j) {
                float z = f[j] + sBf[c0f + j];
                float u = 0.7978845608028654f * (z + 0.044715f * z * z * z);
                float e2u = __expf(2.0f * u);
                float th = 1.0f - 2.0f / (e2u + 1.0f);
                gl[j] = 0.5f * z * (1.0f + th);
            }
        }
        __syncthreads();   // all h reads done before hid overwrites HA region
        {   // store hid at pitch 257 (overlays K/V/HA/P)
            const int c0f = w * 16;
            float* hr = sHid + l * 257 + c0f;
            #pragma unroll
            for (int j = 0; j < 16; ++j) hr[j] = gl[j];
        }
        __syncthreads();
        {   // PR: warp -> 4 cols, lane -> token; 4 split chains (128 each)
            const int c0p = w * 4;
            unsigned long long pa0 = 0, pa1 = 0, pb0 = 0, pb1 = 0;
            const float* hgl = sHid + l * 257;
            #pragma unroll 8
            for (int k = 0; k < 256; k += 2) {
                unsigned long long h0 = bcast2(hgl[k]);
                unsigned long long h1 = bcast2(hgl[k + 1]);
                ulonglong2 w0 = *(const ulonglong2*)&sWp[k * 64 + c0p];
                ulonglong2 w1 = *(const ulonglong2*)&sWp[(k + 1) * 64 + c0p];
                fma2(pa0, h0, w0.x); fma2(pa1, h0, w0.y);
                fma2(pb0, h1, w1.x); fma2(pb1, h1, w1.y);
            }
            add2(pa0, pb0); add2(pa1, pb1);
            float p4[4];
            upk2(pa0, p4[0], p4[1]); upk2(pa1, p4[2], p4[3]);
            float4 bp4 = __ldg((const float4*)(bpr_ + c0p));
            float* xr = sX + l * 65 + c0p;
            xr[0] += 0.1f * (p4[0] + bp4.x);
            xr[1] += 0.1f * (p4[1] + bp4.y);
            xr[2] += 0.1f * (p4[2] + bp4.z);
            xr[3] += 0.1f * (p4[3] + bp4.w);
        }
        {   // prefetch temb for next iter (hides L2 latency behind bar3)
            int itn = (it + 1 < nloops) ? it + 1 : it;
            tv0 = __ldg(g_TEMB + itn * 64 + l);
            tv1 = __ldg(g_TEMB + itn * 64 + 32 + l);
        }
        CLUSTER_BAR();   // bar3: hid reads done before peers push next Q/K/V
    }

    // ================= final LN -> out =================
    {
        float g0 = __ldg(lnfg_ + l), g1 = __ldg(lnfg_ + 32 + l);
        float b0 = __ldg(lnfb_ + l), b1 = __ldg(lnfb_ + 32 + l);
        #pragma unroll
        for (int t = 0; t < 2; ++t) {
            int lt = 2 * w + t;
            float x0 = sX[lt * 65 + l], x1 = sX[lt * 65 + 32 + l];
            float s1 = x0 + x1, s2 = x0 * x0 + x1 * x1;
            #pragma unroll
            for (int o = 16; o; o >>= 1) {
                s1 += __shfl_xor_sync(0xffffffffu, s1, o);
                s2 += __shfl_xor_sync(0xffffffffu, s2, o);
            }
            float mu = s1 * (1.f / 64.f);
            float rs = rsqrtf(s2 * (1.f / 64.f) - mu * mu + 1e-5f);
            out[(t0 + lt) * 64 + l]      = (x0 - mu) * rs * g0 + b0;
            out[(t0 + lt) * 64 + 32 + l] = (x1 - mu) * rs * g1 + b1;
        }
    }
}

extern "C" void kernel_launch(void* const* d_in, const int* in_sizes, int n_in,
                              void* d_out, int out_size)
{
    (void)in_sizes; (void)n_in; (void)out_size;
    cudaFuncSetAttribute(lt37349035606833_kernel,
                         cudaFuncAttributeMaxDynamicSharedMemorySize, SMEM_BYTES);
    lt37349035606833_kernel<<<GRID, NTHREADS, SMEM_BYTES>>>(
        (const int*)  d_in[0],  (const int*)  d_in[1],
        (const float*)d_in[2],  (const float*)d_in[3],
        (const float*)d_in[4],  (const float*)d_in[5],
        (const float*)d_in[6],  (const float*)d_in[7],
        (const float*)d_in[8],  (const float*)d_in[9],
        (const float*)d_in[10], (const float*)d_in[11],
        (const float*)d_in[12], (const float*)d_in[13],
        (const float*)d_in[14], (const float*)d_in[15],
        (const float*)d_in[16], (const float*)d_in[17],
        (const float*)d_in[18], (const float*)d_in[19],
        (const float*)d_in[20], (const float*)d_in[21],
        (float*)d_out);
}

// round 16
// speedup vs baseline: 1.0574x; 1.0574x over previous
#include <cuda_runtime.h>
#include <cstdint>

#define GRID     128
#define NTHREADS 512
#define NT       4096     // B*S tokens

// ---- device globals ----
__device__ float g_TEMB[4096 * 64];
__device__ unsigned g_arrive;
__device__ volatile unsigned g_release;

// ---- smem layout (floats), 58112 = 232448 B (exact max) ----
#define OFF_WQKV 0            // [k][192]      12288
#define OFF_WFC  12288        // [k][256]      16384
#define OFF_WPR  28672        // [k(256)][64]  16384
#define OFF_B    45056        // 448: bqkv[192] bfc[256]
#define OFF_X    45504        // 32 tokens pitch 65 = 2080
#define OFF_Q    47584        // Q[128] pitch 16 = 2048 (peer-pushed, bcast reads)
#define OFF_K    49632        // K[128] pitch 17 = 2176 (peer-pushed)
#define OFF_V    51808        // V[128] pitch 17 = 2176 (peer-pushed)
#define OFF_HA   53984        // h (LN out) / A landing zone, 32x65 = 2080
#define OFF_P    56064        // P2 pair chunks, 16 warps x 128 = 2048
#define OFF_HID  49632        // Phase-C hid 32 x pitch260 = 8320 (overlays K/V/HA/P 8480)
#define SMEM_FLOATS 58112
#define SMEM_BYTES (SMEM_FLOATS * 4)   // 232448

// ---- packed f32x2 helpers ----
__device__ __forceinline__ unsigned long long bcast2(float x) {
    unsigned long long r; asm("mov.b64 %0,{%1,%1};" : "=l"(r) : "f"(x)); return r;
}
__device__ __forceinline__ void upk2(unsigned long long v, float& x, float& y) {
    asm("mov.b64 {%0,%1},%2;" : "=f"(x), "=f"(y) : "l"(v));
}
__device__ __forceinline__ void fma2(unsigned long long& d, unsigned long long a,
                                     unsigned long long b) {
    asm("fma.rn.f32x2 %0,%1,%2,%0;" : "+l"(d) : "l"(a), "l"(b));
}
__device__ __forceinline__ void add2(unsigned long long& d, unsigned long long a) {
    asm("add.rn.f32x2 %0,%0,%1;" : "+l"(d) : "l"(a));
}
__device__ __forceinline__ unsigned long long pack2(float x, float y) {
    unsigned long long r; asm("mov.b64 %0,{%1,%2};" : "=l"(r) : "f"(x), "f"(y)); return r;
}

// ---- cluster helpers ----
__device__ __forceinline__ uint32_t smem_u32(const void* p) {
    uint32_t a;
    asm("{ .reg .u64 t; cvta.to.shared.u64 t, %1; cvt.u32.u64 %0, t; }" : "=r"(a) : "l"(p));
    return a;
}
__device__ __forceinline__ void sts_cluster1(uint32_t laddr, int rank, float v) {
    uint32_t r;
    asm volatile("mapa.shared::cluster.u32 %0, %1, %2;" : "=r"(r) : "r"(laddr), "r"(rank));
    asm volatile("st.shared::cluster.f32 [%0], %1;" :: "r"(r), "f"(v) : "memory");
}
#define CLUSTER_BAR() do { \
    asm volatile("barrier.cluster.arrive.aligned;" ::: "memory"); \
    asm volatile("barrier.cluster.wait.aligned;"   ::: "memory"); \
} while (0)

__device__ __forceinline__ void grid_sync(unsigned gen) {
    __syncthreads();
    if (threadIdx.x == 0) {
        __threadfence();
        unsigned prev = atomicAdd(&g_arrive, 1u);
        if (prev == gen * GRID - 1u) {
            __threadfence();
            g_release = gen;
        } else {
            while (*(volatile unsigned*)&g_release < gen) { __nanosleep(32); }
        }
        __threadfence();
    }
    __syncthreads();
}

extern "C" __global__ void __launch_bounds__(NTHREADS, 1) __cluster_dims__(4, 1, 1)
lt37349035606833_kernel(
    const int*   __restrict__ idx,   const int*   __restrict__ nloops_p,
    const float* __restrict__ wte,   const float* __restrict__ wpe,
    const float* __restrict__ tw1,   const float* __restrict__ tb1,
    const float* __restrict__ tw2,   const float* __restrict__ tb2,
    const float* __restrict__ ln1g_, const float* __restrict__ ln1b_,
    const float* __restrict__ wqkv_, const float* __restrict__ bqkv_,
    const float* __restrict__ wo_,   const float* __restrict__ bo_,
    const float* __restrict__ ln2g_, const float* __restrict__ ln2b_,
    const float* __restrict__ wfc_,  const float* __restrict__ bfc_,
    const float* __restrict__ wpr_,  const float* __restrict__ bpr_,
    const float* __restrict__ lnfg_, const float* __restrict__ lnfb_,
    float* __restrict__ out)
{
    extern __shared__ float sm[];
    const int tid = threadIdx.x;
    const int blk = blockIdx.x;
    const int w = tid >> 5, l = tid & 31;
    const int nloops = *nloops_p;
    unsigned gen = g_release;
    const uint32_t smb = smem_u32(sm);

    // ---- stage weights/biases ----
    for (int i = tid; i < 12288; i += NTHREADS) sm[OFF_WQKV + i] = wqkv_[i];
    for (int i = tid; i < 16384; i += NTHREADS) {
        sm[OFF_WFC + i] = wfc_[i];
        sm[OFF_WPR + i] = wpr_[i];
    }
    if (tid < 192)                sm[OFF_B + tid] = bqkv_[tid];
    if (tid >= 192 && tid < 448)  sm[OFF_B + tid] = bfc_[tid - 192];

    // ln gamma/beta registerized (per-lane)
    const float ln1g0 = __ldg(ln1g_ + l), ln1g1 = __ldg(ln1g_ + 32 + l);
    const float ln1b0 = __ldg(ln1b_ + l), ln1b1 = __ldg(ln1b_ + 32 + l);
    const float ln2g0 = __ldg(ln2g_ + l), ln2g1 = __ldg(ln2g_ + 32 + l);
    const float ln2b0 = __ldg(ln2b_ + l), ln2b1 = __ldg(ln2b_ + 32 + l);

    // ---- initial x tile (pitch 65) ----
    const int t0 = blk * 32;
    for (int i = tid; i < 2048; i += NTHREADS) {
        int t = i >> 6, d = i & 63;
        int tok = t0 + t;
        sm[OFF_X + t * 65 + d] = wte[idx[tok] * 64 + d] + wpe[(tok & 127) * 64 + d];
    }
    __syncthreads();

    // ---- precompute temb (scratch in K/V region; grid_sync below) ----
    {
        float* sT = sm + OFF_K;
        for (int s = blk; s < nloops; s += GRID) {
            float tt = (float)s;
            if (tid < 128) {
                float f = __expf(-9.2103403719761836f * (float)tid / 128.0f);
                float a = tt * f;
                sT[tid]       = cosf(a);
                sT[128 + tid] = sinf(a);
            }
            __syncthreads();
            for (int j = tid; j < 1024; j += NTHREADS) {
                float z = tb1[j];
                for (int k = 0; k < 256; ++k) z += sT[k] * tw1[k * 1024 + j];
                sT[256 + j] = z / (1.0f + __expf(-z));
            }
            __syncthreads();
            if (tid < 64) {
                float z = tb2[tid];
                for (int k = 0; k < 1024; ++k) z += sT[256 + k] * tw2[k * 64 + tid];
                g_TEMB[s * 64 + tid] = z;
            }
            __syncthreads();
        }
    }
    grid_sync(++gen);

    const int rc = blk & 3;                  // cluster rank == head index
    float* sX   = sm + OFF_X;
    float* sHA  = sm + OFF_HA;               // h / A landing zone
    float* sHid = sm + OFF_HID;              // Phase-C hid (overlays K/V/HA/P)
    const float* sQ = sm + OFF_Q;
    const float* sK = sm + OFF_K;
    const float* sV = sm + OFF_V;
    const float* sWq = sm + OFF_WQKV;
    const float* sWf = sm + OFF_WFC;
    const float* sWp = sm + OFF_WPR;
    const float* sBq = sm + OFF_B;
    const float* sBf = sm + OFF_B + 192;

    // temb prefetch for it = 0
    float tv0 = __ldg(g_TEMB + l), tv1 = __ldg(g_TEMB + 32 + l);

    for (int it = 0; it < nloops; ++it) {
        // ============ Phase A: x += temb; LN1 -> sHA; QKV + push ============
        {
            #pragma unroll
            for (int t = 0; t < 2; ++t) {
                int lt = w * 2 + t;
                float x0 = sX[lt * 65 + l]      + tv0;
                float x1 = sX[lt * 65 + 32 + l] + tv1;
                sX[lt * 65 + l]      = x0;
                sX[lt * 65 + 32 + l] = x1;
                float s1 = x0 + x1, s2 = x0 * x0 + x1 * x1;
                #pragma unroll
                for (int o = 16; o; o >>= 1) {
                    s1 += __shfl_xor_sync(0xffffffffu, s1, o);
                    s2 += __shfl_xor_sync(0xffffffffu, s2, o);
                }
                float mu = s1 * (1.0f / 64.0f);
                float rs = rsqrtf(s2 * (1.0f / 64.0f) - mu * mu + 1e-5f);
                sHA[lt * 65 + l]      = (x0 - mu) * rs * ln1g0 + ln1b0;
                sHA[lt * 65 + 32 + l] = (x1 - mu) * rs * ln1g1 + ln1b1;
            }
        }
        __syncthreads();
        {   // QKV GEMM: warp -> 12 cols, lane -> token; push Q/K/V via DSMEM
            const int c0 = w * 12;
            const float* hAl = sHA + l * 65;
            unsigned long long acc[6] = {0, 0, 0, 0, 0, 0};
            #pragma unroll 4
            for (int k = 0; k < 64; ++k) {
                unsigned long long h2 = bcast2(hAl[k]);
                const float* wr = sWq + k * 192 + c0;
                ulonglong2 wa = *(const ulonglong2*)(wr);
                ulonglong2 wb = *(const ulonglong2*)(wr + 4);
                ulonglong2 wc = *(const ulonglong2*)(wr + 8);
                fma2(acc[0], h2, wa.x); fma2(acc[1], h2, wa.y);
                fma2(acc[2], h2, wb.x); fma2(acc[3], h2, wb.y);
                fma2(acc[4], h2, wc.x); fma2(acc[5], h2, wc.y);
            }
            float c[12];
            #pragma unroll
            for (int j = 0; j < 6; ++j) upk2(acc[j], c[2 * j], c[2 * j + 1]);
            const int tkb = rc * 32 + l;     // token within batch (0..127)
            #pragma unroll
            for (int g3 = 0; g3 < 3; ++g3) {
                int cg = c0 + 4 * g3;
                float v0 = c[4*g3]   + sBq[cg];
                float v1 = c[4*g3+1] + sBq[cg+1];
                float v2 = c[4*g3+2] + sBq[cg+2];
                float v3 = c[4*g3+3] + sBq[cg+3];
                uint32_t a; int tr;
                if (cg < 64) {
                    tr = cg >> 4;
                    a = smb + (OFF_Q + tkb * 16 + (cg & 15)) * 4;
                } else if (cg < 128) {
                    tr = (cg - 64) >> 4;
                    a = smb + (OFF_K + tkb * 17 + ((cg - 64) & 15)) * 4;
                } else {
                    tr = (cg - 128) >> 4;
                    a = smb + (OFF_V + tkb * 17 + ((cg - 128) & 15)) * 4;
                }
                sts_cluster1(a,      tr, v0);
                sts_cluster1(a + 4,  tr, v1);
                sts_cluster1(a + 8,  tr, v2);
                sts_cluster1(a + 12, tr, v3);
            }
        }
        CLUSTER_BAR();   // bar1: Q/K/V delivered everywhere

        // ============ Phase B: paired-q attention for head rc ============
        {
            float* sP2 = sm + OFF_P + w * 128;   // 2 groups x 32 key-pairs = 128 floats
            const int d = l & 15, half = l >> 4;
            #pragma unroll 1
            for (int r2 = 0; r2 < 4; ++r2) {
                const int qlo = w + 32 * r2;     // gq(qlo) == gq(qhi) == r2
                const int qhi = qlo + 16;
                const float* qbl = sQ + qlo * 16;
                const float* qbh = sQ + qhi * 16;
                float4 a0 = *(const float4*)(qbl),     a1 = *(const float4*)(qbl + 4);
                float4 a2 = *(const float4*)(qbl + 8), a3 = *(const float4*)(qbl + 12);
                float4 b0 = *(const float4*)(qbh),     b1 = *(const float4*)(qbh + 4);
                float4 b2 = *(const float4*)(qbh + 8), b3 = *(const float4*)(qbh + 12);
                float ql[16] = {a0.x,a0.y,a0.z,a0.w, a1.x,a1.y,a1.z,a1.w,
                                a2.x,a2.y,a2.z,a2.w, a3.x,a3.y,a3.z,a3.w};
                float qh[16] = {b0.x,b0.y,b0.z,b0.w, b1.x,b1.y,b1.z,b1.w,
                                b2.x,b2.y,b2.z,b2.w, b3.x,b3.y,b3.z,b3.w};
                float elo[4], ehi[4];
                float mlo = -1e30f, mhi = -1e30f;
                #pragma unroll
                for (int g = 0; g < 4; ++g) {
                    if (g > r2) break;
                    const float* Kr = sK + (32 * g + l) * 17;
                    float slo = 0.f, shi = 0.f;
                    #pragma unroll
                    for (int dd = 0; dd < 16; ++dd) {
                        float kv = Kr[dd];          // shared K load for both q
                        slo += ql[dd] * kv;
                        shi += qh[dd] * kv;
                    }
                    int key = 32 * g + l;
                    slo = slo * 0.25f + ((key <= qlo) ? 0.f : -1e9f);
                    shi = shi * 0.25f + ((key <= qhi) ? 0.f : -1e9f);
                    elo[g] = slo; mlo = fmaxf(mlo, slo);
                    ehi[g] = shi; mhi = fmaxf(mhi, shi);
                }
                #pragma unroll
                for (int o = 16; o; o >>= 1) {
                    mlo = fmaxf(mlo, __shfl_xor_sync(0xffffffffu, mlo, o));
                    mhi = fmaxf(mhi, __shfl_xor_sync(0xffffffffu, mhi, o));
                }
                float eslo = 0.f, eshi = 0.f;
                #pragma unroll
                for (int g = 0; g < 4; ++g) {
                    if (g > r2) break;
                    elo[g] = __expf(elo[g] - mlo); eslo += elo[g];
                    ehi[g] = __expf(ehi[g] - mhi); eshi += ehi[g];
                }
                #pragma unroll
                for (int o = 16; o; o >>= 1) {
                    eslo += __shfl_xor_sync(0xffffffffu, eslo, o);
                    eshi += __shfl_xor_sync(0xffffffffu, eshi, o);
                }
                float invlo = 1.0f / eslo, invhi = 1.0f / eshi;

                // PV in chunks of <=2 groups; P packed as (Plo,Phi) f32x2
                unsigned long long ov2 = 0;
                const int nchunk = (r2 + 2) >> 1;
                #pragma unroll
                for (int ch = 0; ch < 2; ++ch) {
                    if (ch >= nchunk) break;
                    const int g0 = 2 * ch;
                    const bool two = (g0 + 1 <= r2);
                    // store P pairs: group g0 at [0..64), group g0+1 at [64..128)
                    *(unsigned long long*)(sP2 + 2 * l) =
                        pack2(elo[g0] * invlo, ehi[g0] * invhi);
                    if (two)
                        *(unsigned long long*)(sP2 + 64 + 2 * l) =
                            pack2(elo[g0 + 1] * invlo, ehi[g0 + 1] * invhi);
                    __syncwarp();
                    if (two) {
                        // half h -> group g0+h, key rotation +16h (bank-disjoint)
                        const float* Vg = sV + (32 * (g0 + half)) * 17 + d;
                        const float* Pg = sP2 + half * 64;
                        #pragma unroll 8
                        for (int kk = 0; kk < 32; ++kk) {
                            int key = (kk + 16 * half) & 31;
                            unsigned long long p2 =
                                *(const unsigned long long*)(Pg + 2 * key);
                            fma2(ov2, p2, bcast2(Vg[key * 17]));
                        }
                    } else {
                        // single group: halves split keys 16h..16h+15
                        const float* Vg = sV + (32 * g0) * 17 + d;
                        #pragma unroll 8
                        for (int kk = 0; kk < 16; ++kk) {
                            int key = 16 * half + kk;
                            unsigned long long p2 =
                                *(const unsigned long long*)(sP2 + 2 * key);
                            fma2(ov2, p2, bcast2(Vg[key * 17]));
                        }
                    }
                    __syncwarp();   // P2 consumed before next chunk overwrites
                }
                // combine halves: lane d holds full (ov_lo, ov_hi) after xor-16
                unsigned long long other = __shfl_xor_sync(0xffffffffu, ov2, 16);
                add2(ov2, other);
                if (half == 0) {
                    float ovlo, ovhi;
                    upk2(ov2, ovlo, ovhi);
                    sts_cluster1(smb + (OFF_HA + w * 65 + rc * 16 + d) * 4, r2, ovlo);
                    sts_cluster1(smb + (OFF_HA + (w + 16) * 65 + rc * 16 + d) * 4, r2, ovhi);
                }
                __syncwarp();
            }
        }
        CLUSTER_BAR();   // bar2: A delivered everywhere; Q/K/V/P dead from here

        // ============ Phase C: o-proj + LN2 + MLP (lane = token) ============
        {   // o-proj: warp -> 4 cols, lane -> token; A already in sHA
            const int c0o = w * 4;
            unsigned long long oac[2] = {0, 0};
            const float* sA = sHA + l * 65;
            #pragma unroll 4
            for (int k = 0; k < 64; ++k) {
                unsigned long long a2 = bcast2(sA[k]);
                ulonglong2 wv = __ldg((const ulonglong2*)&wo_[k * 64 + c0o]);
                fma2(oac[0], a2, wv.x); fma2(oac[1], a2, wv.y);
            }
            float o4[4];
            upk2(oac[0], o4[0], o4[1]); upk2(oac[1], o4[2], o4[3]);
            float4 bo4 = __ldg((const float4*)(bo_ + c0o));
            float* xr = sX + l * 65 + c0o;
            xr[0] += 0.1f * (o4[0] + bo4.x);
            xr[1] += 0.1f * (o4[1] + bo4.y);
            xr[2] += 0.1f * (o4[2] + bo4.z);
            xr[3] += 0.1f * (o4[3] + bo4.w);
        }
        __syncthreads();
        {   // LN2: 2 tokens/warp -> h in sHA (A fully consumed)
            #pragma unroll
            for (int t = 0; t < 2; ++t) {
                int lt = 2 * w + t;
                float x0 = sX[lt * 65 + l], x1 = sX[lt * 65 + 32 + l];
                float s1 = x0 + x1, s2 = x0 * x0 + x1 * x1;
                #pragma unroll
                for (int o = 16; o; o >>= 1) {
                    s1 += __shfl_xor_sync(0xffffffffu, s1, o);
                    s2 += __shfl_xor_sync(0xffffffffu, s2, o);
                }
                float mu = s1 * (1.f / 64.f);
                float rs = rsqrtf(s2 * (1.f / 64.f) - mu * mu + 1e-5f);
                sHA[lt * 65 + l]      = (x0 - mu) * rs * ln2g0 + ln2b0;
                sHA[lt * 65 + 32 + l] = (x1 - mu) * rs * ln2g1 + ln2b1;
            }
        }
        __syncthreads();
        float gl[16];
        {   // FC: warp -> 16 cols, lane -> token; gelu in regs
            const int c0f = w * 16;
            unsigned long long fac[8] = {0, 0, 0, 0, 0, 0, 0, 0};
            const float* sH = sHA + l * 65;
            #pragma unroll 2
            for (int k = 0; k < 64; ++k) {
                unsigned long long h2 = bcast2(sH[k]);
                const float* wr = sWf + k * 256 + c0f;
                ulonglong2 wa = *(const ulonglong2*)(wr);
                ulonglong2 wb = *(const ulonglong2*)(wr + 4);
                ulonglong2 wc = *(const ulonglong2*)(wr + 8);
                ulonglong2 wd = *(const ulonglong2*)(wr + 12);
                fma2(fac[0], h2, wa.x); fma2(fac[1], h2, wa.y);
                fma2(fac[2], h2, wb.x); fma2(fac[3], h2, wb.y);
                fma2(fac[4], h2, wc.x); fma2(fac[5], h2, wc.y);
                fma2(fac[6], h2, wd.x); fma2(fac[7], h2, wd.y);
            }
            float f[16];
            #pragma unroll
            for (int j = 0; j < 8; ++j) upk2(fac[j], f[2 * j], f[2 * j + 1]);
            #pragma unroll
            for (int j = 0; j < 16; ++j) {
                float z = f[j] + sBf[c0f + j];
                float u = 0.7978845608028654f * (z + 0.044715f * z * z * z);
                float e2u = __expf(2.0f * u);
                float th = 1.0f - 2.0f / (e2u + 1.0f);
                gl[j] = 0.5f * z * (1.0f + th);
            }
        }
        __syncthreads();   // all h reads done before hid overwrites HA region
        {   // store hid at pitch 260 (16B-aligned rows; overlays K/V/HA/P)
            float* hr = sHid + l * 260 + w * 16;
            *(float4*)(hr)      = make_float4(gl[0],  gl[1],  gl[2],  gl[3]);
            *(float4*)(hr + 4)  = make_float4(gl[4],  gl[5],  gl[6],  gl[7]);
            *(float4*)(hr + 8)  = make_float4(gl[8],  gl[9],  gl[10], gl[11]);
            *(float4*)(hr + 12) = make_float4(gl[12], gl[13], gl[14], gl[15]);
        }
        __syncthreads();
        {   // PR: warp -> 4 cols, lane -> token; hid via float4 loads
            const int c0p = w * 4;
            unsigned long long pa0 = 0, pa1 = 0, pb0 = 0, pb1 = 0;
            const float* hgl = sHid + l * 260;
            #pragma unroll 4
            for (int k = 0; k < 256; k += 4) {
                float4 h4 = *(const float4*)(hgl + k);
                unsigned long long h0 = bcast2(h4.x), h1 = bcast2(h4.y);
                unsigned long long h2 = bcast2(h4.z), h3 = bcast2(h4.w);
                ulonglong2 w0 = *(const ulonglong2*)&sWp[k * 64 + c0p];
                ulonglong2 w1 = *(const ulonglong2*)&sWp[(k + 1) * 64 + c0p];
                ulonglong2 w2 = *(const ulonglong2*)&sWp[(k + 2) * 64 + c0p];
                ulonglong2 w3 = *(const ulonglong2*)&sWp[(k + 3) * 64 + c0p];
                fma2(pa0, h0, w0.x); fma2(pa1, h0, w0.y);
                fma2(pb0, h1, w1.x); fma2(pb1, h1, w1.y);
                fma2(pa0, h2, w2.x); fma2(pa1, h2, w2.y);
                fma2(pb0, h3, w3.x); fma2(pb1, h3, w3.y);
            }
            add2(pa0, pb0); add2(pa1, pb1);
            float p4[4];
            upk2(pa0, p4[0], p4[1]); upk2(pa1, p4[2], p4[3]);
            float4 bp4 = __ldg((const float4*)(bpr_ + c0p));
            float* xr = sX + l * 65 + c0p;
            xr[0] += 0.1f * (p4[0] + bp4.x);
            xr[1] += 0.1f * (p4[1] + bp4.y);
            xr[2] += 0.1f * (p4[2] + bp4.z);
            xr[3] += 0.1f * (p4[3] + bp4.w);
        }
        {   // prefetch temb for next iter
            int itn = (it + 1 < nloops) ? it + 1 : it;
            tv0 = __ldg(g_TEMB + itn * 64 + l);
            tv1 = __ldg(g_TEMB + itn * 64 + 32 + l);
        }
        CLUSTER_BAR();   // bar3: hid reads done before peers push next Q/K/V
    }

    // ================= final LN -> out =================
    {
        float g0 = __ldg(lnfg_ + l), g1 = __ldg(lnfg_ + 32 + l);
        float b0 = __ldg(lnfb_ + l), b1 = __ldg(lnfb_ + 32 + l);
        #pragma unroll
        for (int t = 0; t < 2; ++t) {
            int lt = 2 * w + t;
            float x0 = sX[lt * 65 + l], x1 = sX[lt * 65 + 32 + l];
            float s1 = x0 + x1, s2 = x0 * x0 + x1 * x1;
            #pragma unroll
            for (int o = 16; o; o >>= 1) {
                s1 += __shfl_xor_sync(0xffffffffu, s1, o);
                s2 += __shfl_xor_sync(0xffffffffu, s2, o);
            }
            float mu = s1 * (1.f / 64.f);
            float rs = rsqrtf(s2 * (1.f / 64.f) - mu * mu + 1e-5f);
            out[(t0 + lt) * 64 + l]      = (x0 - mu) * rs * g0 + b0;
            out[(t0 + lt) * 64 + 32 + l] = (x1 - mu) * rs * g1 + b1;
        }
    }
}

extern "C" void kernel_launch(void* const* d_in, const int* in_sizes, int n_in,
                              void* d_out, int out_size)
{
    (void)in_sizes; (void)n_in; (void)out_size;
    cudaFuncSetAttribute(lt37349035606833_kernel,
                         cudaFuncAttributeMaxDynamicSharedMemorySize, SMEM_BYTES);
    lt37349035606833_kernel<<<GRID, NTHREADS, SMEM_BYTES>>>(
        (const int*)  d_in[0],  (const int*)  d_in[1],
        (const float*)d_in[2],  (const float*)d_in[3],
        (const float*)d_in[4],  (const float*)d_in[5],
        (const float*)d_in[6],  (const float*)d_in[7],
        (const float*)d_in[8],  (const float*)d_in[9],
        (const float*)d_in[10], (const float*)d_in[11],
        (const float*)d_in[12], (const float*)d_in[13],
        (const float*)d_in[14], (const float*)d_in[15],
        (const float*)d_in[16], (const float*)d_in[17],
        (const float*)d_in[18], (const float*)d_in[19],
        (const float*)d_in[20], (const float*)d_in[21],
        (float*)d_out);
}

// round 17
// speedup vs baseline: 1.1434x; 1.0813x over previous
#include <cuda_runtime.h>
#include <cstdint>

#define GRID     128
#define NTHREADS 512
#define NT       4096     // B*S tokens

typedef unsigned long long ull;

// ---- device globals ----
__device__ float g_TEMB[4096 * 64];
__device__ unsigned g_arrive;
__device__ volatile unsigned g_release;

// ---- smem layout (floats), 58112 = 232448 B (exact max) ----
#define OFF_WQKV 0            // [k][192]      12288
#define OFF_WFC  12288        // [k][256]      16384
#define OFF_WPR  28672        // [k(256)][64]  16384
#define OFF_B    45056        // 448: bqkv[192] bfc[256]
#define OFF_X    45504        // 32 tokens pitch 65 = 2080
#define OFF_Q    47584        // Q[128] pitch 16 = 2048 (peer-pushed, bcast reads)
#define OFF_K    49632        // K[128] pitch 17 = 2176 (peer-pushed)
#define OFF_V    51808        // V[128] pitch 17 = 2176 (peer-pushed)
#define OFF_HA   53984        // h (LN out) / A landing zone, 32x65 = 2080
#define OFF_P    56064        // P2 pair chunks, 16 warps x 128 = 2048
#define OFF_HID  49632        // Phase-C hid 32 x pitch260 = 8320 (overlays K/V/HA/P 8480)
#define SMEM_FLOATS 58112
#define SMEM_BYTES (SMEM_FLOATS * 4)   // 232448

// ---- packed f32x2 helpers ----
__device__ __forceinline__ ull bcast2(float x) {
    ull r; asm("mov.b64 %0,{%1,%1};" : "=l"(r) : "f"(x)); return r;
}
__device__ __forceinline__ void upk2(ull v, float& x, float& y) {
    asm("mov.b64 {%0,%1},%2;" : "=f"(x), "=f"(y) : "l"(v));
}
__device__ __forceinline__ void fma2(ull& d, ull a, ull b) {
    asm("fma.rn.f32x2 %0,%1,%2,%0;" : "+l"(d) : "l"(a), "l"(b));
}
__device__ __forceinline__ void add2(ull& d, ull a) {
    asm("add.rn.f32x2 %0,%0,%1;" : "+l"(d) : "l"(a));
}
__device__ __forceinline__ ull pack2(float x, float y) {
    ull r; asm("mov.b64 %0,{%1,%2};" : "=l"(r) : "f"(x), "f"(y)); return r;
}

// ---- cluster helpers ----
__device__ __forceinline__ uint32_t smem_u32(const void* p) {
    uint32_t a;
    asm("{ .reg .u64 t; cvta.to.shared.u64 t, %1; cvt.u32.u64 %0, t; }" : "=r"(a) : "l"(p));
    return a;
}
__device__ __forceinline__ uint32_t mapa_u32(uint32_t laddr, int rank) {
    uint32_t r;
    asm("mapa.shared::cluster.u32 %0, %1, %2;" : "=r"(r) : "r"(laddr), "r"(rank));
    return r;
}
__device__ __forceinline__ void stc4(uint32_t ra, float v0, float v1, float v2, float v3) {
    asm volatile("st.shared::cluster.f32 [%0], %1;\n\t"
                 "st.shared::cluster.f32 [%0+4], %2;\n\t"
                 "st.shared::cluster.f32 [%0+8], %3;\n\t"
                 "st.shared::cluster.f32 [%0+12], %4;"
                 :: "r"(ra), "f"(v0), "f"(v1), "f"(v2), "f"(v3) : "memory");
}
__device__ __forceinline__ void stc1(uint32_t ra, float v) {
    asm volatile("st.shared::cluster.f32 [%0], %1;" :: "r"(ra), "f"(v) : "memory");
}
#define CLUSTER_BAR() do { \
    asm volatile("barrier.cluster.arrive.aligned;" ::: "memory"); \
    asm volatile("barrier.cluster.wait.aligned;"   ::: "memory"); \
} while (0)

__device__ __forceinline__ void grid_sync(unsigned gen) {
    __syncthreads();
    if (threadIdx.x == 0) {
        __threadfence();
        unsigned prev = atomicAdd(&g_arrive, 1u);
        if (prev == gen * GRID - 1u) {
            __threadfence();
            g_release = gen;
        } else {
            while (*(volatile unsigned*)&g_release < gen) { __nanosleep(32); }
        }
        __threadfence();
    }
    __syncthreads();
}

extern "C" __global__ void __launch_bounds__(NTHREADS, 1) __cluster_dims__(4, 1, 1)
lt37349035606833_kernel(
    const int*   __restrict__ idx,   const int*   __restrict__ nloops_p,
    const float* __restrict__ wte,   const float* __restrict__ wpe,
    const float* __restrict__ tw1,   const float* __restrict__ tb1,
    const float* __restrict__ tw2,   const float* __restrict__ tb2,
    const float* __restrict__ ln1g_, const float* __restrict__ ln1b_,
    const float* __restrict__ wqkv_, const float* __restrict__ bqkv_,
    const float* __restrict__ wo_,   const float* __restrict__ bo_,
    const float* __restrict__ ln2g_, const float* __restrict__ ln2b_,
    const float* __restrict__ wfc_,  const float* __restrict__ bfc_,
    const float* __restrict__ wpr_,  const float* __restrict__ bpr_,
    const float* __restrict__ lnfg_, const float* __restrict__ lnfb_,
    float* __restrict__ out)
{
    extern __shared__ float sm[];
    const int tid = threadIdx.x;
    const int blk = blockIdx.x;
    const int w = tid >> 5, l = tid & 31;
    const int nloops = *nloops_p;
    unsigned gen = g_release;
    const uint32_t smb = smem_u32(sm);

    // ---- stage weights/biases ----
    for (int i = tid; i < 12288; i += NTHREADS) sm[OFF_WQKV + i] = wqkv_[i];
    for (int i = tid; i < 16384; i += NTHREADS) {
        sm[OFF_WFC + i] = wfc_[i];
        sm[OFF_WPR + i] = wpr_[i];
    }
    if (tid < 192)                sm[OFF_B + tid] = bqkv_[tid];
    if (tid >= 192 && tid < 448)  sm[OFF_B + tid] = bfc_[tid - 192];

    // ln gamma/beta registerized (per-lane)
    const float ln1g0 = __ldg(ln1g_ + l), ln1g1 = __ldg(ln1g_ + 32 + l);
    const float ln1b0 = __ldg(ln1b_ + l), ln1b1 = __ldg(ln1b_ + 32 + l);
    const float ln2g0 = __ldg(ln2g_ + l), ln2g1 = __ldg(ln2g_ + 32 + l);
    const float ln2b0 = __ldg(ln2b_ + l), ln2b1 = __ldg(ln2b_ + 32 + l);

    // ---- initial x tile (pitch 65) ----
    const int t0 = blk * 32;
    for (int i = tid; i < 2048; i += NTHREADS) {
        int t = i >> 6, d = i & 63;
        int tok = t0 + t;
        sm[OFF_X + t * 65 + d] = wte[idx[tok] * 64 + d] + wpe[(tok & 127) * 64 + d];
    }
    __syncthreads();

    // ---- precompute temb (scratch in K/V region; grid_sync below) ----
    {
        float* sT = sm + OFF_K;
        for (int s = blk; s < nloops; s += GRID) {
            float tt = (float)s;
            if (tid < 128) {
                float f = __expf(-9.2103403719761836f * (float)tid / 128.0f);
                float a = tt * f;
                sT[tid]       = cosf(a);
                sT[128 + tid] = sinf(a);
            }
            __syncthreads();
            for (int j = tid; j < 1024; j += NTHREADS) {
                float z = tb1[j];
                for (int k = 0; k < 256; ++k) z += sT[k] * tw1[k * 1024 + j];
                sT[256 + j] = z / (1.0f + __expf(-z));
            }
            __syncthreads();
            if (tid < 64) {
                float z = tb2[tid];
                for (int k = 0; k < 1024; ++k) z += sT[256 + k] * tw2[k * 64 + tid];
                g_TEMB[s * 64 + tid] = z;
            }
            __syncthreads();
        }
    }
    grid_sync(++gen);

    const int rc = blk & 3;                  // cluster rank == head index
    float* sX   = sm + OFF_X;
    float* sHA  = sm + OFF_HA;               // h / A landing zone
    float* sHid = sm + OFF_HID;              // Phase-C hid (overlays K/V/HA/P)
    const float* sQ = sm + OFF_Q;
    const float* sK = sm + OFF_K;
    const float* sV = sm + OFF_V;
    const float* sWq = sm + OFF_WQKV;
    const float* sWf = sm + OFF_WFC;
    const float* sWp = sm + OFF_WPR;
    const float* sBq = sm + OFF_B;
    const float* sBf = sm + OFF_B + 192;

    // ---- precompute QKV push remote addresses (loop-invariant) ----
    uint32_t push_rem[3];
    {
        const int tkb = rc * 32 + l;
        #pragma unroll
        for (int g3 = 0; g3 < 3; ++g3) {
            int cg = w * 12 + 4 * g3;
            uint32_t a; int tr;
            if (cg < 64) {
                tr = cg >> 4;
                a = smb + (OFF_Q + tkb * 16 + (cg & 15)) * 4;
            } else if (cg < 128) {
                tr = (cg - 64) >> 4;
                a = smb + (OFF_K + tkb * 17 + ((cg - 64) & 15)) * 4;
            } else {
                tr = (cg - 128) >> 4;
                a = smb + (OFF_V + tkb * 17 + ((cg - 128) & 15)) * 4;
            }
            push_rem[g3] = mapa_u32(a, tr);
        }
    }
    // HA push local addresses (rank varies per r2; mapa in-loop)
    const uint32_t ha_lo = smb + (OFF_HA + w * 65 + rc * 16 + (l & 15)) * 4;
    const uint32_t ha_hi = ha_lo + 16 * 65 * 4;

    // temb prefetch for it = 0
    float tv0 = __ldg(g_TEMB + l), tv1 = __ldg(g_TEMB + 32 + l);

    for (int it = 0; it < nloops; ++it) {
        // ============ Phase A: x += temb; LN1 -> sHA; QKV + push ============
        {
            #pragma unroll
            for (int t = 0; t < 2; ++t) {
                int lt = w * 2 + t;
                float x0 = sX[lt * 65 + l]      + tv0;
                float x1 = sX[lt * 65 + 32 + l] + tv1;
                sX[lt * 65 + l]      = x0;
                sX[lt * 65 + 32 + l] = x1;
                float s1 = x0 + x1, s2 = x0 * x0 + x1 * x1;
                #pragma unroll
                for (int o = 16; o; o >>= 1) {
                    s1 += __shfl_xor_sync(0xffffffffu, s1, o);
                    s2 += __shfl_xor_sync(0xffffffffu, s2, o);
                }
                float mu = s1 * (1.0f / 64.0f);
                float rs = rsqrtf(s2 * (1.0f / 64.0f) - mu * mu + 1e-5f);
                sHA[lt * 65 + l]      = (x0 - mu) * rs * ln1g0 + ln1b0;
                sHA[lt * 65 + 32 + l] = (x1 - mu) * rs * ln1g1 + ln1b1;
            }
        }
        __syncthreads();
        {   // QKV GEMM: warp -> 12 cols, lane -> token; hoisted-mapa pushes
            const int c0 = w * 12;
            const float* hAl = sHA + l * 65;
            ull acc[6] = {0, 0, 0, 0, 0, 0};
            #pragma unroll 4
            for (int k = 0; k < 64; ++k) {
                ull h2 = bcast2(hAl[k]);
                const float* wr = sWq + k * 192 + c0;
                ulonglong2 wa = *(const ulonglong2*)(wr);
                ulonglong2 wb = *(const ulonglong2*)(wr + 4);
                ulonglong2 wc = *(const ulonglong2*)(wr + 8);
                fma2(acc[0], h2, wa.x); fma2(acc[1], h2, wa.y);
                fma2(acc[2], h2, wb.x); fma2(acc[3], h2, wb.y);
                fma2(acc[4], h2, wc.x); fma2(acc[5], h2, wc.y);
            }
            float c[12];
            #pragma unroll
            for (int j = 0; j < 6; ++j) upk2(acc[j], c[2 * j], c[2 * j + 1]);
            #pragma unroll
            for (int g3 = 0; g3 < 3; ++g3) {
                int cg = c0 + 4 * g3;
                stc4(push_rem[g3],
                     c[4*g3]   + sBq[cg],
                     c[4*g3+1] + sBq[cg+1],
                     c[4*g3+2] + sBq[cg+2],
                     c[4*g3+3] + sBq[cg+3]);
            }
        }
        CLUSTER_BAR();   // bar1: Q/K/V delivered everywhere

        // ============ Phase B: paired-q attention for head rc ============
        {
            float* sP2 = sm + OFF_P + w * 128;
            const int d = l & 15, half = l >> 4;
            #pragma unroll 1
            for (int r2 = 0; r2 < 4; ++r2) {
                const int qlo = w + 32 * r2;     // gq(qlo) == gq(qhi) == r2
                const int qhi = qlo + 16;
                const float* qbl = sQ + qlo * 16;
                const float* qbh = sQ + qhi * 16;
                float4 a0 = *(const float4*)(qbl),     a1 = *(const float4*)(qbl + 4);
                float4 a2 = *(const float4*)(qbl + 8), a3 = *(const float4*)(qbl + 12);
                float4 b0 = *(const float4*)(qbh),     b1 = *(const float4*)(qbh + 4);
                float4 b2 = *(const float4*)(qbh + 8), b3 = *(const float4*)(qbh + 12);
                float ql[16] = {a0.x,a0.y,a0.z,a0.w, a1.x,a1.y,a1.z,a1.w,
                                a2.x,a2.y,a2.z,a2.w, a3.x,a3.y,a3.z,a3.w};
                float qh[16] = {b0.x,b0.y,b0.z,b0.w, b1.x,b1.y,b1.z,b1.w,
                                b2.x,b2.y,b2.z,b2.w, b3.x,b3.y,b3.z,b3.w};
                // scores + exp (no max-sub: LN-bounded; masked -> exp = 0)
                float elo[4], ehi[4];
                float eslo = 0.f, eshi = 0.f;
                #pragma unroll
                for (int g = 0; g < 4; ++g) {
                    if (g > r2) break;
                    const float* Kr = sK + (32 * g + l) * 17;
                    float slo = 0.f, shi = 0.f;
                    #pragma unroll
                    for (int dd = 0; dd < 16; ++dd) {
                        float kv = Kr[dd];          // shared K load for both q
                        slo += ql[dd] * kv;
                        shi += qh[dd] * kv;
                    }
                    int key = 32 * g + l;
                    slo = slo * 0.25f + ((key <= qlo) ? 0.f : -1e9f);
                    shi = shi * 0.25f + ((key <= qhi) ? 0.f : -1e9f);
                    elo[g] = __expf(slo); eslo += elo[g];
                    ehi[g] = __expf(shi); eshi += ehi[g];
                }
                #pragma unroll
                for (int o = 16; o; o >>= 1) {
                    eslo += __shfl_xor_sync(0xffffffffu, eslo, o);
                    eshi += __shfl_xor_sync(0xffffffffu, eshi, o);
                }
                float invlo = 1.0f / eslo, invhi = 1.0f / eshi;

                // PV in chunks of <=2 groups; straight 16-runs (no modular math)
                ull ov2 = 0;
                const int nchunk = (r2 + 2) >> 1;
                #pragma unroll
                for (int ch = 0; ch < 2; ++ch) {
                    if (ch >= nchunk) break;
                    const int g0 = 2 * ch;
                    const bool two = (g0 + 1 <= r2);
                    *(ull*)(sP2 + 2 * l) = pack2(elo[g0] * invlo, ehi[g0] * invhi);
                    if (two)
                        *(ull*)(sP2 + 64 + 2 * l) =
                            pack2(elo[g0 + 1] * invlo, ehi[g0 + 1] * invhi);
                    __syncwarp();
                    if (two) {
                        // half h owns group g0+h; 2 straight 16-runs cover keys 0..31
                        const float* Pg = sP2 + 64 * half;
                        const float* Vg = sV + (32 * (g0 + half)) * 17 + d;
                        const float* P1 = Pg + 32 * half;
                        const float* V1 = Vg + 17 * 16 * half;
                        const float* P2b = Pg + 32 - 32 * half;
                        const float* V2b = Vg + 17 * (16 - 16 * half);
                        #pragma unroll
                        for (int kk = 0; kk < 16; ++kk)
                            fma2(ov2, *(const ull*)(P1 + 2 * kk), bcast2(V1[17 * kk]));
                        #pragma unroll
                        for (int kk = 0; kk < 16; ++kk)
                            fma2(ov2, *(const ull*)(P2b + 2 * kk), bcast2(V2b[17 * kk]));
                    } else {
                        // single group: halves split keys 16h..16h+15
                        const float* P1 = sP2 + 32 * half;
                        const float* V1 = sV + (32 * g0) * 17 + d + 17 * 16 * half;
                        #pragma unroll
                        for (int kk = 0; kk < 16; ++kk)
                            fma2(ov2, *(const ull*)(P1 + 2 * kk), bcast2(V1[17 * kk]));
                    }
                    __syncwarp();   // P2 consumed before next chunk overwrites
                }
                // combine halves
                ull other = __shfl_xor_sync(0xffffffffu, ov2, 16);
                add2(ov2, other);
                if (half == 0) {
                    float ovlo, ovhi;
                    upk2(ov2, ovlo, ovhi);
                    stc1(mapa_u32(ha_lo, r2), ovlo);
                    stc1(mapa_u32(ha_hi, r2), ovhi);
                }
                __syncwarp();
            }
        }
        CLUSTER_BAR();   // bar2: A delivered everywhere; Q/K/V/P dead from here

        // ============ Phase C: o-proj + LN2 + MLP (lane = token) ============
        {   // o-proj: warp -> 4 cols, lane -> token; A already in sHA
            const int c0o = w * 4;
            ull oac[2] = {0, 0};
            const float* sA = sHA + l * 65;
            #pragma unroll 4
            for (int k = 0; k < 64; ++k) {
                ull a2 = bcast2(sA[k]);
                ulonglong2 wv = __ldg((const ulonglong2*)&wo_[k * 64 + c0o]);
                fma2(oac[0], a2, wv.x); fma2(oac[1], a2, wv.y);
            }
            float o4[4];
            upk2(oac[0], o4[0], o4[1]); upk2(oac[1], o4[2], o4[3]);
            float4 bo4 = __ldg((const float4*)(bo_ + c0o));
            float* xr = sX + l * 65 + c0o;
            xr[0] += 0.1f * (o4[0] + bo4.x);
            xr[1] += 0.1f * (o4[1] + bo4.y);
            xr[2] += 0.1f * (o4[2] + bo4.z);
            xr[3] += 0.1f * (o4[3] + bo4.w);
        }
        __syncthreads();
        {   // LN2: 2 tokens/warp -> h in sHA (A fully consumed)
            #pragma unroll
            for (int t = 0; t < 2; ++t) {
                int lt = 2 * w + t;
                float x0 = sX[lt * 65 + l], x1 = sX[lt * 65 + 32 + l];
                float s1 = x0 + x1, s2 = x0 * x0 + x1 * x1;
                #pragma unroll
                for (int o = 16; o; o >>= 1) {
                    s1 += __shfl_xor_sync(0xffffffffu, s1, o);
                    s2 += __shfl_xor_sync(0xffffffffu, s2, o);
                }
                float mu = s1 * (1.f / 64.f);
                float rs = rsqrtf(s2 * (1.f / 64.f) - mu * mu + 1e-5f);
                sHA[lt * 65 + l]      = (x0 - mu) * rs * ln2g0 + ln2b0;
                sHA[lt * 65 + 32 + l] = (x1 - mu) * rs * ln2g1 + ln2b1;
            }
        }
        __syncthreads();
        float gl[16];
        {   // FC: warp -> 16 cols, lane -> token; gelu in regs
            const int c0f = w * 16;
            ull fac[8] = {0, 0, 0, 0, 0, 0, 0, 0};
            const float* sH = sHA + l * 65;
            #pragma unroll 2
            for (int k = 0; k < 64; ++k) {
                ull h2 = bcast2(sH[k]);
                const float* wr = sWf + k * 256 + c0f;
                ulonglong2 wa = *(const ulonglong2*)(wr);
                ulonglong2 wb = *(const ulonglong2*)(wr + 4);
                ulonglong2 wc = *(const ulonglong2*)(wr + 8);
                ulonglong2 wd = *(const ulonglong2*)(wr + 12);
                fma2(fac[0], h2, wa.x); fma2(fac[1], h2, wa.y);
                fma2(fac[2], h2, wb.x); fma2(fac[3], h2, wb.y);
                fma2(fac[4], h2, wc.x); fma2(fac[5], h2, wc.y);
                fma2(fac[6], h2, wd.x); fma2(fac[7], h2, wd.y);
            }
            float f[16];
            #pragma unroll
            for (int j = 0; j < 8; ++j) upk2(fac[j], f[2 * j], f[2 * j + 1]);
            #pragma unroll
            for (int j = 0; j < 16; ++j) {
                float z = f[j] + sBf[c0f + j];
                float u = 0.7978845608028654f * (z + 0.044715f * z * z * z);
                float e2u = __expf(2.0f * u);
                float th = 1.0f - 2.0f / (e2u + 1.0f);
                gl[j] = 0.5f * z * (1.0f + th);
            }
        }
        __syncthreads();   // all h reads done before hid overwrites HA region
        {   // store hid at pitch 260 (16B-aligned rows; overlays K/V/HA/P)
            float* hr = sHid + l * 260 + w * 16;
            *(float4*)(hr)      = make_float4(gl[0],  gl[1],  gl[2],  gl[3]);
            *(float4*)(hr + 4)  = make_float4(gl[4],  gl[5],  gl[6],  gl[7]);
            *(float4*)(hr + 8)  = make_float4(gl[8],  gl[9],  gl[10], gl[11]);
            *(float4*)(hr + 12) = make_float4(gl[12], gl[13], gl[14], gl[15]);
        }
        __syncthreads();
        {   // PR: warp -> 4 cols, lane -> token; hid via float4 loads
            const int c0p = w * 4;
            ull pa0 = 0, pa1 = 0, pb0 = 0, pb1 = 0;
            const float* hgl = sHid + l * 260;
            #pragma unroll 4
            for (int k = 0; k < 256; k += 4) {
                float4 h4 = *(const float4*)(hgl + k);
                ull h0 = bcast2(h4.x), h1 = bcast2(h4.y);
                ull h2 = bcast2(h4.z), h3 = bcast2(h4.w);
                ulonglong2 w0 = *(const ulonglong2*)&sWp[k * 64 + c0p];
                ulonglong2 w1 = *(const ulonglong2*)&sWp[(k + 1) * 64 + c0p];
                ulonglong2 w2 = *(const ulonglong2*)&sWp[(k + 2) * 64 + c0p];
                ulonglong2 w3 = *(const ulonglong2*)&sWp[(k + 3) * 64 + c0p];
                fma2(pa0, h0, w0.x); fma2(pa1, h0, w0.y);
                fma2(pb0, h1, w1.x); fma2(pb1, h1, w1.y);
                fma2(pa0, h2, w2.x); fma2(pa1, h2, w2.y);
                fma2(pb0, h3, w3.x); fma2(pb1, h3, w3.y);
            }
            add2(pa0, pb0); add2(pa1, pb1);
            float p4[4];
            upk2(pa0, p4[0], p4[1]); upk2(pa1, p4[2], p4[3]);
            float4 bp4 = __ldg((const float4*)(bpr_ + c0p));
            float* xr = sX + l * 65 + c0p;
            xr[0] += 0.1f * (p4[0] + bp4.x);
            xr[1] += 0.1f * (p4[1] + bp4.y);
            xr[2] += 0.1f * (p4[2] + bp4.z);
            xr[3] += 0.1f * (p4[3] + bp4.w);
        }
        {   // prefetch temb for next iter
            int itn = (it + 1 < nloops) ? it + 1 : it;
            tv0 = __ldg(g_TEMB + itn * 64 + l);
            tv1 = __ldg(g_TEMB + itn * 64 + 32 + l);
        }
        CLUSTER_BAR();   // bar3: hid reads done before peers push next Q/K/V
    }

    // ================= final LN -> out =================
    {
        float g0 = __ldg(lnfg_ + l), g1 = __ldg(lnfg_ + 32 + l);
        float b0 = __ldg(lnfb_ + l), b1 = __ldg(lnfb_ + 32 + l);
        #pragma unroll
        for (int t = 0; t < 2; ++t) {
            int lt = 2 * w + t;
            float x0 = sX[lt * 65 + l], x1 = sX[lt * 65 + 32 + l];
            float s1 = x0 + x1, s2 = x0 * x0 + x1 * x1;
            #pragma unroll
            for (int o = 16; o; o >>= 1) {
                s1 += __shfl_xor_sync(0xffffffffu, s1, o);
                s2 += __shfl_xor_sync(0xffffffffu, s2, o);
            }
            float mu = s1 * (1.f / 64.f);
            float rs = rsqrtf(s2 * (1.f / 64.f) - mu * mu + 1e-5f);
            out[(t0 + lt) * 64 + l]      = (x0 - mu) * rs * g0 + b0;
            out[(t0 + lt) * 64 + 32 + l] = (x1 - mu) * rs * g1 + b1;
        }
    }
}

extern "C" void kernel_launch(void* const* d_in, const int* in_sizes, int n_in,
                              void* d_out, int out_size)
{
    (void)in_sizes; (void)n_in; (void)out_size;
    cudaFuncSetAttribute(lt37349035606833_kernel,
                         cudaFuncAttributeMaxDynamicSharedMemorySize, SMEM_BYTES);
    lt37349035606833_kernel<<<GRID, NTHREADS, SMEM_BYTES>>>(
        (const int*)  d_in[0],  (const int*)  d_in[1],
        (const float*)d_in[2],  (const float*)d_in[3],
        (const float*)d_in[4],  (const float*)d_in[5],
        (const float*)d_in[6],  (const float*)d_in[7],
        (const float*)d_in[8],  (const float*)d_in[9],
        (const float*)d_in[10], (const float*)d_in[11],
        (const float*)d_in[12], (const float*)d_in[13],
        (const float*)d_in[14], (const float*)d_in[15],
        (const float*)d_in[16], (const float*)d_in[17],
        (const float*)d_in[18], (const float*)d_in[19],
        (const float*)d_in[20], (const float*)d_in[21],
        (float*)d_out);
}